// round 10
// baseline (speedup 1.0000x reference)
#include <cuda_runtime.h>
#include <math.h>
#include <float.h>

#define BSZ 8
#define NP  1024
#define KNB 20
#define CT  169
#define EPSF 1e-6f
#define NT  8

// ---------------- scratch (device globals; no runtime allocation) ----------------
__device__ float  g_h[BSZ * 3 * NP];
__device__ float  g_xx[BSZ * NP];
__device__ float  g_dist[(size_t)BSZ * NP * NP];           // 32 MB distance matrix (L2-resident)
__device__ int    g_idx[BSZ * NP * KNB];
__device__ float  g_feat[BSZ * CT * 3 * NP];               // x1|x2|x3|x4 concat channels
__device__ float  g_p[(size_t)BSZ * 341 * 3 * NP];         // p5 (layer-5 GEMM out)
__device__ float  g_d[(size_t)BSZ * 3 * NP];               // d5
__device__ double g_stats[682];
__device__ float  g_mu[341];
__device__ float  g_rstd[341];

// ---------------- kernels ----------------

__global__ void transpose_x_kernel(const float* __restrict__ x) {
    int i = blockIdx.x * blockDim.x + threadIdx.x;   // over B*N*3
    if (i >= BSZ * NP * 3) return;
    int e = i % 3;
    int n = (i / 3) % NP;
    int b = i / (3 * NP);
    g_h[(b * 3 + e) * NP + n] = x[i];
}

__global__ void xx_kernel(const float* __restrict__ f, int bstride, int D) {
    int b = blockIdx.y;
    int n = blockIdx.x * blockDim.x + threadIdx.x;
    const float* fb = f + (size_t)b * bstride;
    float s = 0.f;
    for (int d = 0; d < D; d++) {
        float v = fb[d * NP + n];
        s += v * v;
    }
    g_xx[b * NP + n] = s;
}

// pd[b][i][j] = 2*dot(f_i,f_j) - xx_i - xx_j   (== reference formula)
__global__ void knn_dist_kernel(const float* __restrict__ f, int bstride, int D) {
    __shared__ float sI[8][32];
    __shared__ float sJ[8][32];
    int b  = blockIdx.z;
    int j0 = blockIdx.x * 32;
    int i0 = blockIdx.y * 32;
    int tx = threadIdx.x, ty = threadIdx.y;
    const float* fb = f + (size_t)b * bstride;
    float acc[4] = {0.f, 0.f, 0.f, 0.f};
    for (int d0 = 0; d0 < D; d0 += 8) {
        int d = d0 + ty;
        sI[ty][tx] = (d < D) ? fb[d * NP + i0 + tx] : 0.f;
        sJ[ty][tx] = (d < D) ? fb[d * NP + j0 + tx] : 0.f;
        __syncthreads();
#pragma unroll
        for (int dd = 0; dd < 8; dd++) {
            float vj = sJ[dd][tx];
#pragma unroll
            for (int r = 0; r < 4; r++) acc[r] += sI[dd][ty + 8 * r] * vj;
        }
        __syncthreads();
    }
    float xj = g_xx[b * NP + j0 + tx];
#pragma unroll
    for (int r = 0; r < 4; r++) {
        int i = i0 + ty + 8 * r;
        g_dist[((size_t)b * NP + i) * NP + j0 + tx] = 2.f * acc[r] - g_xx[b * NP + i] - xj;
    }
}

// warp-per-row top-K via radix threshold select (register-resident, no spills).
// Selected set == jax.lax.top_k set (ties -> lowest index). Output order is
// arbitrary, which is fine: all consumers mean-pool over k.
__global__ void knn_topk_kernel() {
    int gw   = blockIdx.x * (blockDim.x >> 5) + (threadIdx.x >> 5);
    int lane = threadIdx.x & 31;
    if (gw >= BSZ * NP) return;
    const float* dr = &g_dist[(size_t)gw * NP];

    unsigned u[NP / 32];
#pragma unroll
    for (int t = 0; t < NP / 32; t++) {
        unsigned bb = __float_as_uint(dr[lane + 32 * t]);
        u[t] = (bb & 0x80000000u) ? ~bb : (bb | 0x80000000u);
    }

    unsigned T = 0u;
#pragma unroll
    for (int bit = 31; bit >= 0; bit--) {
        unsigned cand = T | (1u << bit);
        int c = 0;
#pragma unroll
        for (int t = 0; t < NP / 32; t++) c += (u[t] >= cand) ? 1 : 0;
        c = __reduce_add_sync(0xffffffffu, c);
        if (c >= KNB) T = cand;
    }

    int cg = 0;
#pragma unroll
    for (int t = 0; t < NP / 32; t++) cg += (u[t] > T) ? 1 : 0;
    int totalg = __reduce_add_sync(0xffffffffu, cg);

    int* row = &g_idx[gw * KNB];
    unsigned below = (1u << lane) - 1u;
    int pos = 0;
    int quota_eq = KNB - totalg;
    int eq_taken = 0;
#pragma unroll
    for (int t = 0; t < NP / 32; t++) {
        bool g = (u[t] > T), e = (u[t] == T);
        unsigned mg = __ballot_sync(0xffffffffu, g);
        unsigned me = __ballot_sync(0xffffffffu, e);
        if (g) row[pos + __popc(mg & below)] = lane + 32 * t;
        pos += __popc(mg);
        if (e) {
            int r = eq_taken + __popc(me & below);
            if (r < quota_eq) row[totalg + r] = lane + 32 * t;
        }
        eq_taken += __popc(me);
    }
}

__global__ void zero_stats_kernel() {
    int i = threadIdx.x;
    if (i < 682) g_stats[i] = 0.0;
}

// stats pass: thread = (o, e), 20 k-accumulators in registers; compute p ONLY,
// accumulate BN norm statistics; no bulk global stores.
__global__ void __launch_bounds__(256) stats_kernel(
        const float* __restrict__ feat, int bstride, int C, int Cout,
        const float* __restrict__ wf) {
    extern __shared__ float sm[];
    float* sWa   = sm;                      // Cout*C
    float* sWdel = sWa + Cout * C;          // Cout*C
    float* sCtr  = sWdel + Cout * C;        // C*3
    float* sNbr  = sCtr + C * 3;            // KNB*C*3
    float* sP    = sNbr + KNB * C * 3;      // KNB*Cout*3

    int tid = threadIdx.x;
    int b   = blockIdx.y;
    int n0  = blockIdx.x * NT;
    int o = tid / 3, e = tid % 3;
    bool act = (tid < Cout * 3);
    int C3 = C * 3;

    for (int i = tid; i < Cout * C; i += blockDim.x) {
        int oo = i / C, c = i % C;
        float a  = wf[oo * 2 * C + c];
        sWa[i]   = a;
        sWdel[i] = wf[oo * 2 * C + C + c] - a;
    }

    const float* F = feat + (size_t)b * bstride;
    const int* idxr0 = &g_idx[(b * NP + n0) * KNB];
    double s1 = 0.0, s2 = 0.0;

    for (int nn = 0; nn < NT; nn++) {
        int n = n0 + nn;
        const int* idxr = idxr0 + nn * KNB;
        __syncthreads();
        for (int i = tid; i < C3; i += blockDim.x) sCtr[i] = F[(size_t)i * NP + n];
        for (int i = tid; i < KNB * C3; i += blockDim.x) {
            int k = i / C3, r = i - k * C3;
            int j = idxr[k];
            sNbr[i] = F[(size_t)r * NP + j];
        }
        __syncthreads();

        if (act) {
            float accP[KNB];
            float pc = 0.f;
            const float* wrD = &sWdel[o * C];
            for (int c = 0; c < C; c++) pc += wrD[c] * sCtr[c * 3 + e];
#pragma unroll
            for (int k = 0; k < KNB; k++) accP[k] = pc;

            const float* wr = &sWa[o * C];
            for (int c = 0; c < C; c++) {
                float w = wr[c];
                const float* nb = &sNbr[c * 3 + e];
#pragma unroll
                for (int k = 0; k < KNB; k++) accP[k] += w * nb[k * C3];
            }
#pragma unroll
            for (int k = 0; k < KNB; k++) sP[k * Cout * 3 + tid] = accP[k];
        }
        __syncthreads();
        if (tid < Cout) {
#pragma unroll
            for (int k = 0; k < KNB; k++) {
                const float* pp = &sP[k * Cout * 3 + tid * 3];
                float nor = sqrtf(pp[0] * pp[0] + pp[1] * pp[1] + pp[2] * pp[2]) + EPSF;
                s1 += (double)nor;
                s2 += (double)nor * (double)nor;
            }
        }
    }
    if (tid < Cout) {
        atomicAdd(&g_stats[tid], s1);
        atomicAdd(&g_stats[341 + tid], s2);
    }
}

__global__ void bn_finalize_kernel(int Cout, double inv_count) {
    int o = blockIdx.x * blockDim.x + threadIdx.x;
    if (o >= Cout) return;
    double mu  = g_stats[o] * inv_count;
    double var = g_stats[341 + o] * inv_count - mu * mu;
    g_mu[o]   = (float)mu;
    g_rstd[o] = (float)(1.0 / sqrt(var + 1e-5));
}

// fused pass: recompute p and d per edge (identical op order as stats pass),
// stage per-point (p,d) in shared, then BN + VN-LeakyReLU + mean over k ->
// write into concat feature buffer. No per-edge global traffic.
__global__ void __launch_bounds__(256) fused_kernel(
        const float* __restrict__ feat, int bstride, int C, int Cout, int cbase_out,
        const float* __restrict__ wf, const float* __restrict__ wd,
        const float* __restrict__ gamma, const float* __restrict__ beta) {
    extern __shared__ float sm[];
    float* sWa   = sm;                      // Cout*C
    float* sWdel = sWa + Cout * C;
    float* sDa   = sWdel + Cout * C;
    float* sDdel = sDa + Cout * C;
    float* sCtr  = sDdel + Cout * C;        // C*3
    float* sNbr  = sCtr + C * 3;            // KNB*C*3
    float* sP    = sNbr + KNB * C * 3;      // KNB*Cout*3
    float* sD    = sP + KNB * Cout * 3;     // KNB*Cout*3

    int tid = threadIdx.x;
    int b   = blockIdx.y;
    int n0  = blockIdx.x * NT;
    int o = tid / 3, e = tid % 3;
    bool act = (tid < Cout * 3);
    int C3 = C * 3;

    for (int i = tid; i < Cout * C; i += blockDim.x) {
        int oo = i / C, c = i % C;
        float a  = wf[oo * 2 * C + c];
        sWa[i]   = a;
        sWdel[i] = wf[oo * 2 * C + C + c] - a;
        float da = wd[oo * 2 * C + c];
        sDa[i]   = da;
        sDdel[i] = wd[oo * 2 * C + C + c] - da;
    }

    const float* F = feat + (size_t)b * bstride;
    const int* idxr0 = &g_idx[(b * NP + n0) * KNB];

    for (int nn = 0; nn < NT; nn++) {
        int n = n0 + nn;
        const int* idxr = idxr0 + nn * KNB;
        __syncthreads();
        for (int i = tid; i < C3; i += blockDim.x) sCtr[i] = F[(size_t)i * NP + n];
        for (int i = tid; i < KNB * C3; i += blockDim.x) {
            int k = i / C3, r = i - k * C3;
            int j = idxr[k];
            sNbr[i] = F[(size_t)r * NP + j];
        }
        __syncthreads();

        if (act) {
            float accP[KNB], accQ[KNB];
            float pc = 0.f, qc = 0.f;
            const float* wrD = &sWdel[o * C];
            const float* vrD = &sDdel[o * C];
            for (int c = 0; c < C; c++) {
                float fv = sCtr[c * 3 + e];
                pc += wrD[c] * fv;
                qc += vrD[c] * fv;
            }
#pragma unroll
            for (int k = 0; k < KNB; k++) { accP[k] = pc; accQ[k] = qc; }

            const float* wr = &sWa[o * C];
            const float* vr = &sDa[o * C];
            for (int c = 0; c < C; c++) {
                float w = wr[c], v = vr[c];
                const float* nb = &sNbr[c * 3 + e];
#pragma unroll
                for (int k = 0; k < KNB; k++) {
                    float fv = nb[k * C3];
                    accP[k] += w * fv;
                    accQ[k] += v * fv;
                }
            }
#pragma unroll
            for (int k = 0; k < KNB; k++) {
                sP[k * Cout * 3 + tid] = accP[k];
                sD[k * Cout * 3 + tid] = accQ[k];
            }
        }
        __syncthreads();

        if (tid < Cout) {
            float mu = g_mu[tid], rstd = g_rstd[tid], gm = gamma[tid], bt = beta[tid];
            float a0 = 0.f, a1 = 0.f, a2 = 0.f;
#pragma unroll
            for (int k = 0; k < KNB; k++) {
                const float* pp = &sP[k * Cout * 3 + tid * 3];
                const float* dd = &sD[k * Cout * 3 + tid * 3];
                float p0 = pp[0], p1 = pp[1], p2 = pp[2];
                float d0 = dd[0], d1 = dd[1], d2 = dd[2];
                float nor = sqrtf(p0 * p0 + p1 * p1 + p2 * p2) + EPSF;
                float s = ((nor - mu) * rstd * gm + bt) / nor;
                p0 *= s; p1 *= s; p2 *= s;
                float dot = p0 * d0 + p1 * d1 + p2 * d2;
                if (dot >= 0.f) {
                    a0 += p0; a1 += p1; a2 += p2;
                } else {
                    float dsq = d0 * d0 + d1 * d1 + d2 * d2;
                    float f = 0.8f * dot / (dsq + EPSF);
                    a0 += p0 - f * d0; a1 += p1 - f * d1; a2 += p2 - f * d2;
                }
            }
            const float inv = 1.f / (float)KNB;
            float* FO = g_feat + ((size_t)b * CT + cbase_out + tid) * 3 * NP;
            FO[0 * NP + n] = a0 * inv;
            FO[1 * NP + n] = a1 * inv;
            FO[2 * NP + n] = a2 * inv;
        }
    }
}

// layer 5: p5[b] (341x3072) = w5 (341x169) @ feat[b] (169x3072), into g_p
// 64x64 tile, 4x4 register micro-tile per thread (16x16 threads).
__global__ void __launch_bounds__(256) gemm_l5_kernel(const float* __restrict__ w5) {
    __shared__ float As[64][17];     // [m][k]
    __shared__ float Bs[16][64];     // [k][n]
    int b = blockIdx.z;
    const float* Bm = g_feat + (size_t)b * CT * 3 * NP;
    float* Cm = g_p + (size_t)b * 341 * 3072;
    int tid = threadIdx.x;
    int tx = tid & 15, ty = tid >> 4;
    int m0 = blockIdx.y * 64;
    int n0 = blockIdx.x * 64;
    float acc[4][4] = {};
    for (int k0 = 0; k0 < CT; k0 += 16) {
        for (int i = tid; i < 64 * 16; i += 256) {
            int k = i & 15, m = i >> 4;
            int gm_ = m0 + m, gk = k0 + k;
            As[m][k] = (gm_ < 341 && gk < CT) ? w5[gm_ * CT + gk] : 0.f;
        }
        for (int i = tid; i < 16 * 64; i += 256) {
            int nn = i & 63, k = i >> 6;
            int gk = k0 + k;
            Bs[k][nn] = (gk < CT) ? Bm[(size_t)gk * 3072 + n0 + nn] : 0.f;
        }
        __syncthreads();
#pragma unroll
        for (int kk = 0; kk < 16; kk++) {
            float a0 = As[ty * 4 + 0][kk];
            float a1 = As[ty * 4 + 1][kk];
            float a2 = As[ty * 4 + 2][kk];
            float a3 = As[ty * 4 + 3][kk];
            float b0 = Bs[kk][tx * 4 + 0];
            float b1 = Bs[kk][tx * 4 + 1];
            float b2 = Bs[kk][tx * 4 + 2];
            float b3 = Bs[kk][tx * 4 + 3];
            acc[0][0] += a0 * b0; acc[0][1] += a0 * b1; acc[0][2] += a0 * b2; acc[0][3] += a0 * b3;
            acc[1][0] += a1 * b0; acc[1][1] += a1 * b1; acc[1][2] += a1 * b2; acc[1][3] += a1 * b3;
            acc[2][0] += a2 * b0; acc[2][1] += a2 * b1; acc[2][2] += a2 * b2; acc[2][3] += a2 * b3;
            acc[3][0] += a3 * b0; acc[3][1] += a3 * b1; acc[3][2] += a3 * b2; acc[3][3] += a3 * b3;
        }
        __syncthreads();
    }
#pragma unroll
    for (int r = 0; r < 4; r++) {
        int gm_ = m0 + ty * 4 + r;
        if (gm_ < 341) {
#pragma unroll
            for (int s = 0; s < 4; s++)
                Cm[(size_t)gm_ * 3072 + n0 + tx * 4 + s] = acc[r][s];
        }
    }
}

__global__ void d5_kernel(const float* __restrict__ wd5) {
    int i = blockIdx.x * blockDim.x + threadIdx.x;   // B*3*N
    if (i >= BSZ * 3 * NP) return;
    int n = i % NP;
    int e = (i / NP) % 3;
    int b = i / (3 * NP);
    const float* F = g_feat + (size_t)b * CT * 3 * NP;
    float a = 0.f;
    for (int c = 0; c < CT; c++) a += wd5[c] * F[(size_t)(c * 3 + e) * NP + n];
    g_d[(size_t)b * 3072 + e * NP + n] = a;
}

__global__ void stats5_kernel() {
    int o = blockIdx.x, b = blockIdx.y;
    const float* P = g_p + ((size_t)b * 341 + o) * 3072;
    double s1 = 0.0, s2 = 0.0;
    for (int n = threadIdx.x; n < NP; n += blockDim.x) {
        float p0 = P[n], p1 = P[NP + n], p2 = P[2 * NP + n];
        float nor = sqrtf(p0 * p0 + p1 * p1 + p2 * p2) + EPSF;
        s1 += (double)nor;
        s2 += (double)nor * (double)nor;
    }
#pragma unroll
    for (int off = 16; off > 0; off >>= 1) {
        s1 += __shfl_down_sync(0xffffffff, s1, off);
        s2 += __shfl_down_sync(0xffffffff, s2, off);
    }
    if ((threadIdx.x & 31) == 0) {
        atomicAdd(&g_stats[o], s1);
        atomicAdd(&g_stats[341 + o], s2);
    }
}

__global__ void pass2_l5_kernel(float* __restrict__ out,
                                const float* __restrict__ gamma, const float* __restrict__ beta) {
    int i = blockIdx.x * blockDim.x + threadIdx.x;  // over B*341*N
    if (i >= BSZ * 341 * NP) return;
    int n = i % NP;
    int o = (i / NP) % 341;
    int b = i / (341 * NP);
    const float* P = g_p + ((size_t)b * 341 + o) * 3072;
    const float* D = g_d + (size_t)b * 3072;
    float p0 = P[n], p1 = P[NP + n], p2 = P[2 * NP + n];
    float d0 = D[n], d1 = D[NP + n], d2 = D[2 * NP + n];
    float nor = sqrtf(p0 * p0 + p1 * p1 + p2 * p2) + EPSF;
    float s = ((nor - g_mu[o]) * g_rstd[o] * gamma[o] + beta[o]) / nor;
    p0 *= s; p1 *= s; p2 *= s;
    float dot = p0 * d0 + p1 * d1 + p2 * d2;
    float v0, v1, v2;
    if (dot >= 0.f) {
        v0 = p0; v1 = p1; v2 = p2;
    } else {
        float dsq = d0 * d0 + d1 * d1 + d2 * d2;
        float f = 0.8f * dot / (dsq + EPSF);
        v0 = p0 - f * d0; v1 = p1 - f * d1; v2 = p2 - f * d2;
    }
    size_t ob = ((size_t)b * 341 + o) * 3072;
    out[ob + 0 * NP + n] = v0;
    out[ob + 1 * NP + n] = v1;
    out[ob + 2 * NP + n] = v2;
}

// ---------------- launch ----------------
extern "C" void kernel_launch(void* const* d_in, const int* in_sizes, int n_in,
                              void* d_out, int out_size) {
    const float* x = (const float*)d_in[0];
    const float *W[5], *Dw[5], *G[5], *Bt[5];
    for (int l = 0; l < 5; l++) {
        W[l]  = (const float*)d_in[1 + 4 * l];
        Dw[l] = (const float*)d_in[2 + 4 * l];
        G[l]  = (const float*)d_in[3 + 4 * l];
        Bt[l] = (const float*)d_in[4 + 4 * l];
    }
    float* out = (float*)d_out;

    void* pv;
    cudaGetSymbolAddress(&pv, g_h);
    float* hptr = (float*)pv;
    cudaGetSymbolAddress(&pv, g_feat);
    float* fptr = (float*)pv;

    cudaFuncSetAttribute(stats_kernel, cudaFuncAttributeMaxDynamicSharedMemorySize, 120 * 1024);
    cudaFuncSetAttribute(fused_kernel, cudaFuncAttributeMaxDynamicSharedMemorySize, 120 * 1024);

    transpose_x_kernel<<<96, 256>>>(x);

    struct LayerCfg { const float* feat; int D; int C; int Cout; int cbo; };
    LayerCfg L[4] = {
        { hptr,                 3,   1,  21, 0  },
        { fptr,                 63,  21, 21, 21 },
        { fptr + 21 * 3 * NP,   63,  21, 42, 42 },
        { fptr + 42 * 3 * NP,   126, 42, 85, 84 },
    };

    for (int l = 0; l < 4; l++) {
        int bstride = (l == 0) ? 3 * NP : CT * 3 * NP;
        xx_kernel<<<dim3(NP / 256, BSZ), 256>>>(L[l].feat, bstride, L[l].D);
        knn_dist_kernel<<<dim3(NP / 32, NP / 32, BSZ), dim3(32, 8)>>>(L[l].feat, bstride, L[l].D);
        knn_topk_kernel<<<BSZ * NP * 32 / 256, 256>>>();
        zero_stats_kernel<<<1, 682>>>();
        int C = L[l].C, Co = L[l].Cout;
        size_t smem_s = (size_t)(2 * Co * C + C * 3 + KNB * C * 3 + KNB * Co * 3) * sizeof(float);
        stats_kernel<<<dim3(NP / NT, BSZ), 256, smem_s>>>(L[l].feat, bstride, C, Co, W[l]);
        bn_finalize_kernel<<<3, 128>>>(Co, 1.0 / ((double)BSZ * NP * KNB));
        size_t smem_f = (size_t)(4 * Co * C + C * 3 + KNB * C * 3 + 2 * KNB * Co * 3) * sizeof(float);
        fused_kernel<<<dim3(NP / NT, BSZ), 256, smem_f>>>(L[l].feat, bstride, C, Co, L[l].cbo,
                                                          W[l], Dw[l], G[l], Bt[l]);
    }

    // layer 5
    zero_stats_kernel<<<1, 682>>>();
    gemm_l5_kernel<<<dim3(3072 / 64, (341 + 63) / 64, BSZ), 256>>>(W[4]);
    d5_kernel<<<96, 256>>>(Dw[4]);
    stats5_kernel<<<dim3(341, BSZ), 256>>>();
    bn_finalize_kernel<<<3, 128>>>(341, 1.0 / ((double)BSZ * NP));
    pass2_l5_kernel<<<(BSZ * 341 * NP + 255) / 256, 256>>>(out, G[4], Bt[4]);
}

// round 11
// speedup vs baseline: 1.8186x; 1.8186x over previous
#include <cuda_runtime.h>
#include <math.h>
#include <float.h>

#define BSZ 8
#define NP  1024
#define KNB 20
#define CT  169
#define EPSF 1e-6f
#define NT  8

// ---------------- scratch (device globals; no runtime allocation) ----------------
__device__ float  g_h[BSZ * 3 * NP];
__device__ float  g_xx[BSZ * NP];
__device__ float  g_dist[(size_t)BSZ * NP * NP];           // 32 MB distance matrix (L2-resident)
__device__ int    g_idx[BSZ * NP * KNB];
__device__ float  g_feat[BSZ * CT * 3 * NP];               // channel-major concat (knn_dist / l5)
__device__ float  g_featT[BSZ * NP * CT * 3];              // point-major concat (pass1 staging)
__device__ float  g_p[(size_t)BSZ * NP * KNB * 85 * 3];    // per-edge p (reused as p5)
__device__ float  g_d[(size_t)BSZ * NP * KNB * 85 * 3];    // per-edge d (reused as d5)
__device__ double g_stats[682];
__device__ float  g_mu[341];
__device__ float  g_rstd[341];

// ---------------- kernels ----------------

__global__ void transpose_x_kernel(const float* __restrict__ x) {
    int i = blockIdx.x * blockDim.x + threadIdx.x;   // over B*N*3
    if (i >= BSZ * NP * 3) return;
    int e = i % 3;
    int n = (i / 3) % NP;
    int b = i / (3 * NP);
    g_h[(b * 3 + e) * NP + n] = x[i];
}

__global__ void xx_kernel(const float* __restrict__ f, int bstride, int D) {
    int b = blockIdx.y;
    int n = blockIdx.x * blockDim.x + threadIdx.x;
    const float* fb = f + (size_t)b * bstride;
    float s = 0.f;
    for (int d = 0; d < D; d++) {
        float v = fb[d * NP + n];
        s += v * v;
    }
    g_xx[b * NP + n] = s;
}

// pd[b][i][j] = 2*dot(f_i,f_j) - xx_i - xx_j   (== reference formula)
__global__ void knn_dist_kernel(const float* __restrict__ f, int bstride, int D) {
    __shared__ float sI[8][32];
    __shared__ float sJ[8][32];
    int b  = blockIdx.z;
    int j0 = blockIdx.x * 32;
    int i0 = blockIdx.y * 32;
    int tx = threadIdx.x, ty = threadIdx.y;
    const float* fb = f + (size_t)b * bstride;
    float acc[4] = {0.f, 0.f, 0.f, 0.f};
    for (int d0 = 0; d0 < D; d0 += 8) {
        int d = d0 + ty;
        sI[ty][tx] = (d < D) ? fb[d * NP + i0 + tx] : 0.f;
        sJ[ty][tx] = (d < D) ? fb[d * NP + j0 + tx] : 0.f;
        __syncthreads();
#pragma unroll
        for (int dd = 0; dd < 8; dd++) {
            float vj = sJ[dd][tx];
#pragma unroll
            for (int r = 0; r < 4; r++) acc[r] += sI[dd][ty + 8 * r] * vj;
        }
        __syncthreads();
    }
    float xj = g_xx[b * NP + j0 + tx];
#pragma unroll
    for (int r = 0; r < 4; r++) {
        int i = i0 + ty + 8 * r;
        g_dist[((size_t)b * NP + i) * NP + j0 + tx] = 2.f * acc[r] - g_xx[b * NP + i] - xj;
    }
}

// warp-per-row top-K via radix threshold select (register-resident, no spills).
// Selected set == jax.lax.top_k set (ties -> lowest index). Output order is
// arbitrary, which is fine: all consumers mean-pool over k.
__global__ void knn_topk_kernel() {
    int gw   = blockIdx.x * (blockDim.x >> 5) + (threadIdx.x >> 5);
    int lane = threadIdx.x & 31;
    if (gw >= BSZ * NP) return;
    const float* dr = &g_dist[(size_t)gw * NP];

    unsigned u[NP / 32];
#pragma unroll
    for (int t = 0; t < NP / 32; t++) {
        unsigned bb = __float_as_uint(dr[lane + 32 * t]);
        u[t] = (bb & 0x80000000u) ? ~bb : (bb | 0x80000000u);
    }

    unsigned T = 0u;
#pragma unroll
    for (int bit = 31; bit >= 0; bit--) {
        unsigned cand = T | (1u << bit);
        int c = 0;
#pragma unroll
        for (int t = 0; t < NP / 32; t++) c += (u[t] >= cand) ? 1 : 0;
        c = __reduce_add_sync(0xffffffffu, c);
        if (c >= KNB) T = cand;
    }

    int cg = 0;
#pragma unroll
    for (int t = 0; t < NP / 32; t++) cg += (u[t] > T) ? 1 : 0;
    int totalg = __reduce_add_sync(0xffffffffu, cg);

    int* row = &g_idx[gw * KNB];
    unsigned below = (1u << lane) - 1u;
    int pos = 0;
    int quota_eq = KNB - totalg;
    int eq_taken = 0;
#pragma unroll
    for (int t = 0; t < NP / 32; t++) {
        bool g = (u[t] > T), e = (u[t] == T);
        unsigned mg = __ballot_sync(0xffffffffu, g);
        unsigned me = __ballot_sync(0xffffffffu, e);
        if (g) row[pos + __popc(mg & below)] = lane + 32 * t;
        pos += __popc(mg);
        if (e) {
            int r = eq_taken + __popc(me & below);
            if (r < quota_eq) row[totalg + r] = lane + 32 * t;
        }
        eq_taken += __popc(me);
    }
}

__global__ void zero_stats_kernel() {
    int i = threadIdx.x;
    if (i < 682) g_stats[i] = 0.0;
}

// pass1: thread = (o, e), 20 k-accumulators in registers.
// Stages ctr + all 20 nbrs from the POINT-MAJOR feature copy (fully coalesced),
// computes p & d, stores them coalesced to g_p/g_d, accumulates norm stats.
// FT layout: point stride `ps` floats; this layer's channels start at `cbase3`.
__global__ void __launch_bounds__(256) pass1_kernel(
        const float* __restrict__ FT, int ps, int cbase3, int C, int Cout,
        const float* __restrict__ wf, const float* __restrict__ wd) {
    extern __shared__ float sm[];
    float* sWa   = sm;                      // Cout*C
    float* sWdel = sWa + Cout * C;
    float* sDa   = sWdel + Cout * C;
    float* sDdel = sDa + Cout * C;
    float* sCtr  = sDdel + Cout * C;        // C*3
    float* sNbr  = sCtr + C * 3;            // KNB * C*3
    float* sP    = sNbr + KNB * C * 3;      // KNB * Cout*3

    int tid = threadIdx.x;
    int b   = blockIdx.y;
    int n0  = blockIdx.x * NT;
    int o = tid / 3, e = tid % 3;
    bool act = (tid < Cout * 3);
    int C3 = C * 3;

    for (int i = tid; i < Cout * C; i += blockDim.x) {
        int oo = i / C, c = i % C;
        float a  = wf[oo * 2 * C + c];
        sWa[i]   = a;
        sWdel[i] = wf[oo * 2 * C + C + c] - a;
        float da = wd[oo * 2 * C + c];
        sDa[i]   = da;
        sDdel[i] = wd[oo * 2 * C + C + c] - da;
    }

    const int* idxr0 = &g_idx[(b * NP + n0) * KNB];
    double s1 = 0.0, s2 = 0.0;

    for (int nn = 0; nn < NT; nn++) {
        int n = n0 + nn;
        const int* idxr = idxr0 + nn * KNB;
        __syncthreads();   // prior iter's stats (sP) and compute (sNbr) complete
        {
            const float* Pt = FT + (size_t)(b * NP + n) * ps + cbase3;
            for (int i = tid; i < C3; i += blockDim.x) sCtr[i] = Pt[i];
        }
        for (int i = tid; i < KNB * C3; i += blockDim.x) {
            int k = i / C3, r = i - k * C3;
            int j = idxr[k];                    // tiny row, L1-resident
            sNbr[i] = FT[(size_t)(b * NP + j) * ps + cbase3 + r];   // coalesced in r
        }
        __syncthreads();

        if (act) {
            float accP[KNB], accQ[KNB];
            float pc = 0.f, qc = 0.f;
            const float* wrD = &sWdel[o * C];
            const float* vrD = &sDdel[o * C];
            for (int c = 0; c < C; c++) {
                float fv = sCtr[c * 3 + e];
                pc += wrD[c] * fv;
                qc += vrD[c] * fv;
            }
#pragma unroll
            for (int k = 0; k < KNB; k++) { accP[k] = pc; accQ[k] = qc; }

            const float* wr = &sWa[o * C];
            const float* vr = &sDa[o * C];
            for (int c = 0; c < C; c++) {
                float w = wr[c], v = vr[c];
                const float* nb = &sNbr[c * 3 + e];
#pragma unroll
                for (int k = 0; k < KNB; k++) {
                    float fv = nb[k * C3];
                    accP[k] += w * fv;
                    accQ[k] += v * fv;
                }
            }
            size_t base0 = (((size_t)(b * NP + n)) * KNB) * Cout * 3 + tid;
#pragma unroll
            for (int k = 0; k < KNB; k++) {
                size_t base = base0 + (size_t)k * Cout * 3;
                g_p[base] = accP[k];
                g_d[base] = accQ[k];
                sP[k * Cout * 3 + tid] = accP[k];
            }
        }
        __syncthreads();
        if (tid < Cout) {
#pragma unroll
            for (int k = 0; k < KNB; k++) {
                const float* pp = &sP[k * Cout * 3 + tid * 3];
                float nor = sqrtf(pp[0] * pp[0] + pp[1] * pp[1] + pp[2] * pp[2]) + EPSF;
                s1 += (double)nor;
                s2 += (double)nor * (double)nor;
            }
        }
    }
    if (tid < Cout) {
        atomicAdd(&g_stats[tid], s1);
        atomicAdd(&g_stats[341 + tid], s2);
    }
}

__global__ void bn_finalize_kernel(int Cout, double inv_count) {
    int o = blockIdx.x * blockDim.x + threadIdx.x;
    if (o >= Cout) return;
    double mu  = g_stats[o] * inv_count;
    double var = g_stats[341 + o] * inv_count - mu * mu;
    g_mu[o]   = (float)mu;
    g_rstd[o] = (float)(1.0 / sqrt(var + 1e-5));
}

// pass2: BN + VN-LeakyReLU + mean over k -> writes BOTH feature layouts
__global__ void pass2_kernel(int cbase_out, int Cout,
                             const float* __restrict__ gamma, const float* __restrict__ beta) {
    int b = blockIdx.y, n = blockIdx.x;
    int o = threadIdx.x;
    if (o >= Cout) return;
    float mu = g_mu[o], rstd = g_rstd[o], gm = gamma[o], bt = beta[o];
    float a0 = 0, a1 = 0, a2 = 0;
    for (int k = 0; k < KNB; k++) {
        size_t base = ((((size_t)(b * NP + n)) * KNB + k) * Cout + o) * 3;
        float p0 = g_p[base], p1 = g_p[base + 1], p2 = g_p[base + 2];
        float d0 = g_d[base], d1 = g_d[base + 1], d2 = g_d[base + 2];
        float nor = sqrtf(p0 * p0 + p1 * p1 + p2 * p2) + EPSF;
        float s = ((nor - mu) * rstd * gm + bt) / nor;
        p0 *= s; p1 *= s; p2 *= s;
        float dot = p0 * d0 + p1 * d1 + p2 * d2;
        if (dot >= 0.f) {
            a0 += p0; a1 += p1; a2 += p2;
        } else {
            float dsq = d0 * d0 + d1 * d1 + d2 * d2;
            float f = 0.8f * dot / (dsq + EPSF);
            a0 += p0 - f * d0; a1 += p1 - f * d1; a2 += p2 - f * d2;
        }
    }
    const float inv = 1.f / (float)KNB;
    a0 *= inv; a1 *= inv; a2 *= inv;
    float* FO = g_feat + ((size_t)b * CT + cbase_out + o) * 3 * NP;
    FO[0 * NP + n] = a0;
    FO[1 * NP + n] = a1;
    FO[2 * NP + n] = a2;
    float* FT = g_featT + ((size_t)(b * NP + n) * CT + cbase_out + o) * 3;
    FT[0] = a0;
    FT[1] = a1;
    FT[2] = a2;
}

// layer 5: p5[b] (341x3072) = w5 (341x169) @ feat[b] (169x3072), into g_p
// 64x64 tile, 4x4 register micro-tile per thread (16x16 threads).
__global__ void __launch_bounds__(256) gemm_l5_kernel(const float* __restrict__ w5) {
    __shared__ float As[64][17];     // [m][k]
    __shared__ float Bs[16][64];     // [k][n]
    int b = blockIdx.z;
    const float* Bm = g_feat + (size_t)b * CT * 3 * NP;
    float* Cm = g_p + (size_t)b * 341 * 3072;
    int tid = threadIdx.x;
    int tx = tid & 15, ty = tid >> 4;
    int m0 = blockIdx.y * 64;
    int n0 = blockIdx.x * 64;
    float acc[4][4] = {};
    for (int k0 = 0; k0 < CT; k0 += 16) {
        for (int i = tid; i < 64 * 16; i += 256) {
            int k = i & 15, m = i >> 4;
            int gm_ = m0 + m, gk = k0 + k;
            As[m][k] = (gm_ < 341 && gk < CT) ? w5[gm_ * CT + gk] : 0.f;
        }
        for (int i = tid; i < 16 * 64; i += 256) {
            int nn = i & 63, k = i >> 6;
            int gk = k0 + k;
            Bs[k][nn] = (gk < CT) ? Bm[(size_t)gk * 3072 + n0 + nn] : 0.f;
        }
        __syncthreads();
#pragma unroll
        for (int kk = 0; kk < 16; kk++) {
            float a0 = As[ty * 4 + 0][kk];
            float a1 = As[ty * 4 + 1][kk];
            float a2 = As[ty * 4 + 2][kk];
            float a3 = As[ty * 4 + 3][kk];
            float b0 = Bs[kk][tx * 4 + 0];
            float b1 = Bs[kk][tx * 4 + 1];
            float b2 = Bs[kk][tx * 4 + 2];
            float b3 = Bs[kk][tx * 4 + 3];
            acc[0][0] += a0 * b0; acc[0][1] += a0 * b1; acc[0][2] += a0 * b2; acc[0][3] += a0 * b3;
            acc[1][0] += a1 * b0; acc[1][1] += a1 * b1; acc[1][2] += a1 * b2; acc[1][3] += a1 * b3;
            acc[2][0] += a2 * b0; acc[2][1] += a2 * b1; acc[2][2] += a2 * b2; acc[2][3] += a2 * b3;
            acc[3][0] += a3 * b0; acc[3][1] += a3 * b1; acc[3][2] += a3 * b2; acc[3][3] += a3 * b3;
        }
        __syncthreads();
    }
#pragma unroll
    for (int r = 0; r < 4; r++) {
        int gm_ = m0 + ty * 4 + r;
        if (gm_ < 341) {
#pragma unroll
            for (int s = 0; s < 4; s++)
                Cm[(size_t)gm_ * 3072 + n0 + tx * 4 + s] = acc[r][s];
        }
    }
}

__global__ void d5_kernel(const float* __restrict__ wd5) {
    int i = blockIdx.x * blockDim.x + threadIdx.x;   // B*3*N
    if (i >= BSZ * 3 * NP) return;
    int n = i % NP;
    int e = (i / NP) % 3;
    int b = i / (3 * NP);
    const float* F = g_feat + (size_t)b * CT * 3 * NP;
    float a = 0.f;
    for (int c = 0; c < CT; c++) a += wd5[c] * F[(size_t)(c * 3 + e) * NP + n];
    g_d[(size_t)b * 3072 + e * NP + n] = a;
}

__global__ void stats5_kernel() {
    int o = blockIdx.x, b = blockIdx.y;
    const float* P = g_p + ((size_t)b * 341 + o) * 3072;
    double s1 = 0.0, s2 = 0.0;
    for (int n = threadIdx.x; n < NP; n += blockDim.x) {
        float p0 = P[n], p1 = P[NP + n], p2 = P[2 * NP + n];
        float nor = sqrtf(p0 * p0 + p1 * p1 + p2 * p2) + EPSF;
        s1 += (double)nor;
        s2 += (double)nor * (double)nor;
    }
#pragma unroll
    for (int off = 16; off > 0; off >>= 1) {
        s1 += __shfl_down_sync(0xffffffff, s1, off);
        s2 += __shfl_down_sync(0xffffffff, s2, off);
    }
    if ((threadIdx.x & 31) == 0) {
        atomicAdd(&g_stats[o], s1);
        atomicAdd(&g_stats[341 + o], s2);
    }
}

__global__ void pass2_l5_kernel(float* __restrict__ out,
                                const float* __restrict__ gamma, const float* __restrict__ beta) {
    int i = blockIdx.x * blockDim.x + threadIdx.x;  // over B*341*N
    if (i >= BSZ * 341 * NP) return;
    int n = i % NP;
    int o = (i / NP) % 341;
    int b = i / (341 * NP);
    const float* P = g_p + ((size_t)b * 341 + o) * 3072;
    const float* D = g_d + (size_t)b * 3072;
    float p0 = P[n], p1 = P[NP + n], p2 = P[2 * NP + n];
    float d0 = D[n], d1 = D[NP + n], d2 = D[2 * NP + n];
    float nor = sqrtf(p0 * p0 + p1 * p1 + p2 * p2) + EPSF;
    float s = ((nor - g_mu[o]) * g_rstd[o] * gamma[o] + beta[o]) / nor;
    p0 *= s; p1 *= s; p2 *= s;
    float dot = p0 * d0 + p1 * d1 + p2 * d2;
    float v0, v1, v2;
    if (dot >= 0.f) {
        v0 = p0; v1 = p1; v2 = p2;
    } else {
        float dsq = d0 * d0 + d1 * d1 + d2 * d2;
        float f = 0.8f * dot / (dsq + EPSF);
        v0 = p0 - f * d0; v1 = p1 - f * d1; v2 = p2 - f * d2;
    }
    size_t ob = ((size_t)b * 341 + o) * 3072;
    out[ob + 0 * NP + n] = v0;
    out[ob + 1 * NP + n] = v1;
    out[ob + 2 * NP + n] = v2;
}

// ---------------- launch ----------------
extern "C" void kernel_launch(void* const* d_in, const int* in_sizes, int n_in,
                              void* d_out, int out_size) {
    const float* x = (const float*)d_in[0];
    const float *W[5], *Dw[5], *G[5], *Bt[5];
    for (int l = 0; l < 5; l++) {
        W[l]  = (const float*)d_in[1 + 4 * l];
        Dw[l] = (const float*)d_in[2 + 4 * l];
        G[l]  = (const float*)d_in[3 + 4 * l];
        Bt[l] = (const float*)d_in[4 + 4 * l];
    }
    float* out = (float*)d_out;

    void* pv;
    cudaGetSymbolAddress(&pv, g_h);
    float* hptr = (float*)pv;
    cudaGetSymbolAddress(&pv, g_feat);
    float* fptr = (float*)pv;
    cudaGetSymbolAddress(&pv, g_featT);
    float* ftptr = (float*)pv;

    cudaFuncSetAttribute(pass1_kernel, cudaFuncAttributeMaxDynamicSharedMemorySize, 100 * 1024);

    transpose_x_kernel<<<96, 256>>>(x);

    // knn_dist feat (channel-major), pass1 FT (point-major)
    struct LayerCfg { const float* feat; const float* ft; int ps; int cb3; int D; int C; int Cout; int cbo; };
    LayerCfg L[4] = {
        { hptr,               x,     3,      0,      3,   1,  21, 0  },
        { fptr,               ftptr, CT * 3, 0,      63,  21, 21, 21 },
        { fptr + 21 * 3 * NP, ftptr, CT * 3, 21 * 3, 63,  21, 42, 42 },
        { fptr + 42 * 3 * NP, ftptr, CT * 3, 42 * 3, 126, 42, 85, 84 },
    };

    for (int l = 0; l < 4; l++) {
        int bstride = (l == 0) ? 3 * NP : CT * 3 * NP;
        xx_kernel<<<dim3(NP / 256, BSZ), 256>>>(L[l].feat, bstride, L[l].D);
        knn_dist_kernel<<<dim3(NP / 32, NP / 32, BSZ), dim3(32, 8)>>>(L[l].feat, bstride, L[l].D);
        knn_topk_kernel<<<BSZ * NP * 32 / 256, 256>>>();
        zero_stats_kernel<<<1, 682>>>();
        int C = L[l].C, Co = L[l].Cout;
        size_t smem = (size_t)(4 * Co * C + C * 3 + KNB * C * 3 + KNB * Co * 3) * sizeof(float);
        pass1_kernel<<<dim3(NP / NT, BSZ), 256, smem>>>(L[l].ft, L[l].ps, L[l].cb3, C, Co, W[l], Dw[l]);
        bn_finalize_kernel<<<3, 128>>>(Co, 1.0 / ((double)BSZ * NP * KNB));
        int p2threads = ((Co + 31) / 32) * 32;
        pass2_kernel<<<dim3(NP, BSZ), p2threads>>>(L[l].cbo, Co, G[l], Bt[l]);
    }

    // layer 5
    zero_stats_kernel<<<1, 682>>>();
    gemm_l5_kernel<<<dim3(3072 / 64, (341 + 63) / 64, BSZ), 256>>>(W[4]);
    d5_kernel<<<96, 256>>>(Dw[4]);
    stats5_kernel<<<dim3(341, BSZ), 256>>>();
    bn_finalize_kernel<<<3, 128>>>(341, 1.0 / ((double)BSZ * NP));
    pass2_l5_kernel<<<(BSZ * 341 * NP + 255) / 256, 256>>>(out, G[4], Bt[4]);
}

// round 12
// speedup vs baseline: 1.8903x; 1.0394x over previous
#include <cuda_runtime.h>
#include <math.h>
#include <float.h>

#define BSZ 8
#define NP  1024
#define KNB 20
#define CT  169
#define EPSF 1e-6f
#define NT  8
#define RPB 8    // rows per block in fused knn

// ---------------- scratch (device globals; no runtime allocation) ----------------
__device__ float  g_h[BSZ * 3 * NP];
__device__ float  g_xx[BSZ * NP];
__device__ int    g_idx[BSZ * NP * KNB];
__device__ float  g_feat[BSZ * CT * 3 * NP];               // channel-major concat (knn / l5)
__device__ float  g_featT[BSZ * NP * CT * 3];              // point-major concat (pass1 staging)
__device__ float  g_p[(size_t)BSZ * NP * KNB * 85 * 3];    // per-edge p (reused as p5)
__device__ float  g_d[(size_t)BSZ * NP * KNB * 85 * 3];    // per-edge d (reused as d5)
__device__ double g_stats[682];
__device__ float  g_mu[341];
__device__ float  g_rstd[341];

// ---------------- kernels ----------------

__global__ void transpose_x_kernel(const float* __restrict__ x) {
    int i = blockIdx.x * blockDim.x + threadIdx.x;   // over B*N*3
    if (i >= BSZ * NP * 3) return;
    int e = i % 3;
    int n = (i / 3) % NP;
    int b = i / (3 * NP);
    g_h[(b * 3 + e) * NP + n] = x[i];
}

__global__ void xx_kernel(const float* __restrict__ f, int bstride, int D) {
    int b = blockIdx.y;
    int n = blockIdx.x * blockDim.x + threadIdx.x;
    const float* fb = f + (size_t)b * bstride;
    float s = 0.f;
    for (int d = 0; d < D; d++) {
        float v = fb[d * NP + n];
        s += v * v;
    }
    g_xx[b * NP + n] = s;
}

// Fused KNN: distance GEMM (register-tiled 8 rows x 4 j per lane) + radix top-K,
// all in one kernel; no distance matrix in global memory.
// dist[i][j] = 2*dot(f_i,f_j) - xx_i - xx_j (same op order as reference path).
__global__ void __launch_bounds__(256) knn_fused_kernel(const float* __restrict__ f,
                                                        int bstride, int D) {
    extern __shared__ float sm[];
    float* sI  = sm;               // [D][RPB] i-features
    float* sXX = sm + D * RPB;     // [NP]
    float* sJ  = sXX + NP;         // [8][NP] j-feature tile, reused as dist buf [RPB][NP]

    int tid = threadIdx.x;
    int b = blockIdx.y, i0 = blockIdx.x * RPB;
    const float* fb = f + (size_t)b * bstride;

    for (int i = tid; i < D * RPB; i += 256) {
        int d = i / RPB, r = i - d * RPB;
        sI[i] = fb[d * NP + i0 + r];
    }
    for (int j = tid; j < NP; j += 256) sXX[j] = g_xx[b * NP + j];

    int w = tid >> 5, lane = tid & 31;
    int jb = w * 128 + lane * 4;      // this lane's 4 j-columns
    float acc[RPB][4];
#pragma unroll
    for (int r = 0; r < RPB; r++)
#pragma unroll
        for (int q = 0; q < 4; q++) acc[r][q] = 0.f;

    for (int d0 = 0; d0 < D; d0 += 8) {
        int dt = D - d0; if (dt > 8) dt = 8;
        __syncthreads();
        for (int i = tid; i < dt * NP; i += 256)
            sJ[i] = fb[(size_t)(d0 + (i >> 10)) * NP + (i & (NP - 1))];
        __syncthreads();
        for (int dd = 0; dd < dt; dd++) {
            float4 jv = *(const float4*)&sJ[dd * NP + jb];
            const float* iv = &sI[(d0 + dd) * RPB];
            float4 iva = *(const float4*)&iv[0];
            float4 ivb = *(const float4*)&iv[4];
            acc[0][0] += iva.x * jv.x; acc[0][1] += iva.x * jv.y; acc[0][2] += iva.x * jv.z; acc[0][3] += iva.x * jv.w;
            acc[1][0] += iva.y * jv.x; acc[1][1] += iva.y * jv.y; acc[1][2] += iva.y * jv.z; acc[1][3] += iva.y * jv.w;
            acc[2][0] += iva.z * jv.x; acc[2][1] += iva.z * jv.y; acc[2][2] += iva.z * jv.z; acc[2][3] += iva.z * jv.w;
            acc[3][0] += iva.w * jv.x; acc[3][1] += iva.w * jv.y; acc[3][2] += iva.w * jv.z; acc[3][3] += iva.w * jv.w;
            acc[4][0] += ivb.x * jv.x; acc[4][1] += ivb.x * jv.y; acc[4][2] += ivb.x * jv.z; acc[4][3] += ivb.x * jv.w;
            acc[5][0] += ivb.y * jv.x; acc[5][1] += ivb.y * jv.y; acc[5][2] += ivb.y * jv.z; acc[5][3] += ivb.y * jv.w;
            acc[6][0] += ivb.z * jv.x; acc[6][1] += ivb.z * jv.y; acc[6][2] += ivb.z * jv.z; acc[6][3] += ivb.z * jv.w;
            acc[7][0] += ivb.w * jv.x; acc[7][1] += ivb.w * jv.y; acc[7][2] += ivb.w * jv.z; acc[7][3] += ivb.w * jv.w;
        }
    }

    // finalize distances into the (reused) smem buffer
    __syncthreads();
    float xj0 = sXX[jb + 0], xj1 = sXX[jb + 1], xj2 = sXX[jb + 2], xj3 = sXX[jb + 3];
#pragma unroll
    for (int r = 0; r < RPB; r++) {
        float xi = g_xx[b * NP + i0 + r];
        float4 o;
        o.x = 2.f * acc[r][0] - xi - xj0;
        o.y = 2.f * acc[r][1] - xi - xj1;
        o.z = 2.f * acc[r][2] - xi - xj2;
        o.w = 2.f * acc[r][3] - xi - xj3;
        *(float4*)&sJ[r * NP + jb] = o;
    }
    __syncthreads();

    // radix top-K: warp w handles row w (set == jax.lax.top_k set; ties -> lowest index)
    const float* dr = &sJ[w * NP];
    unsigned u[NP / 32];
#pragma unroll
    for (int t = 0; t < NP / 32; t++) {
        unsigned bb = __float_as_uint(dr[lane + 32 * t]);
        u[t] = (bb & 0x80000000u) ? ~bb : (bb | 0x80000000u);
    }
    unsigned T = 0u;
#pragma unroll
    for (int bit = 31; bit >= 0; bit--) {
        unsigned cand = T | (1u << bit);
        int c = 0;
#pragma unroll
        for (int t = 0; t < NP / 32; t++) c += (u[t] >= cand) ? 1 : 0;
        c = __reduce_add_sync(0xffffffffu, c);
        if (c >= KNB) T = cand;
    }
    int cg = 0;
#pragma unroll
    for (int t = 0; t < NP / 32; t++) cg += (u[t] > T) ? 1 : 0;
    int totalg = __reduce_add_sync(0xffffffffu, cg);

    int gw = b * NP + i0 + w;
    int* row = &g_idx[gw * KNB];
    unsigned below = (1u << lane) - 1u;
    int pos = 0;
    int quota_eq = KNB - totalg;
    int eq_taken = 0;
#pragma unroll
    for (int t = 0; t < NP / 32; t++) {
        bool g = (u[t] > T), e = (u[t] == T);
        unsigned mg = __ballot_sync(0xffffffffu, g);
        unsigned me = __ballot_sync(0xffffffffu, e);
        if (g) row[pos + __popc(mg & below)] = lane + 32 * t;
        pos += __popc(mg);
        if (e) {
            int r = eq_taken + __popc(me & below);
            if (r < quota_eq) row[totalg + r] = lane + 32 * t;
        }
        eq_taken += __popc(me);
    }
}

__global__ void zero_stats_kernel() {
    int i = threadIdx.x;
    if (i < 682) g_stats[i] = 0.0;
}

// pass1: thread = (o, e), 20 k-accumulators in registers.
// Stages ctr + all 20 nbrs from the POINT-MAJOR feature copy (fully coalesced),
// computes p & d, stores them coalesced to g_p/g_d, accumulates norm stats.
__global__ void __launch_bounds__(256) pass1_kernel(
        const float* __restrict__ FT, int ps, int cbase3, int C, int Cout,
        const float* __restrict__ wf, const float* __restrict__ wd) {
    extern __shared__ float sm[];
    float* sWa   = sm;                      // Cout*C
    float* sWdel = sWa + Cout * C;
    float* sDa   = sWdel + Cout * C;
    float* sDdel = sDa + Cout * C;
    float* sCtr  = sDdel + Cout * C;        // C*3
    float* sNbr  = sCtr + C * 3;            // KNB * C*3
    float* sP    = sNbr + KNB * C * 3;      // KNB * Cout*3

    int tid = threadIdx.x;
    int b   = blockIdx.y;
    int n0  = blockIdx.x * NT;
    int o = tid / 3, e = tid % 3;
    bool act = (tid < Cout * 3);
    int C3 = C * 3;

    for (int i = tid; i < Cout * C; i += blockDim.x) {
        int oo = i / C, c = i % C;
        float a  = wf[oo * 2 * C + c];
        sWa[i]   = a;
        sWdel[i] = wf[oo * 2 * C + C + c] - a;
        float da = wd[oo * 2 * C + c];
        sDa[i]   = da;
        sDdel[i] = wd[oo * 2 * C + C + c] - da;
    }

    const int* idxr0 = &g_idx[(b * NP + n0) * KNB];
    double s1 = 0.0, s2 = 0.0;

    for (int nn = 0; nn < NT; nn++) {
        int n = n0 + nn;
        const int* idxr = idxr0 + nn * KNB;
        __syncthreads();
        {
            const float* Pt = FT + (size_t)(b * NP + n) * ps + cbase3;
            for (int i = tid; i < C3; i += blockDim.x) sCtr[i] = Pt[i];
        }
        for (int i = tid; i < KNB * C3; i += blockDim.x) {
            int k = i / C3, r = i - k * C3;
            int j = idxr[k];
            sNbr[i] = FT[(size_t)(b * NP + j) * ps + cbase3 + r];
        }
        __syncthreads();

        if (act) {
            float accP[KNB], accQ[KNB];
            float pc = 0.f, qc = 0.f;
            const float* wrD = &sWdel[o * C];
            const float* vrD = &sDdel[o * C];
            for (int c = 0; c < C; c++) {
                float fv = sCtr[c * 3 + e];
                pc += wrD[c] * fv;
                qc += vrD[c] * fv;
            }
#pragma unroll
            for (int k = 0; k < KNB; k++) { accP[k] = pc; accQ[k] = qc; }

            const float* wr = &sWa[o * C];
            const float* vr = &sDa[o * C];
            for (int c = 0; c < C; c++) {
                float w = wr[c], v = vr[c];
                const float* nb = &sNbr[c * 3 + e];
#pragma unroll
                for (int k = 0; k < KNB; k++) {
                    float fv = nb[k * C3];
                    accP[k] += w * fv;
                    accQ[k] += v * fv;
                }
            }
            size_t base0 = (((size_t)(b * NP + n)) * KNB) * Cout * 3 + tid;
#pragma unroll
            for (int k = 0; k < KNB; k++) {
                size_t base = base0 + (size_t)k * Cout * 3;
                g_p[base] = accP[k];
                g_d[base] = accQ[k];
                sP[k * Cout * 3 + tid] = accP[k];
            }
        }
        __syncthreads();
        if (tid < Cout) {
#pragma unroll
            for (int k = 0; k < KNB; k++) {
                const float* pp = &sP[k * Cout * 3 + tid * 3];
                float nor = sqrtf(pp[0] * pp[0] + pp[1] * pp[1] + pp[2] * pp[2]) + EPSF;
                s1 += (double)nor;
                s2 += (double)nor * (double)nor;
            }
        }
    }
    if (tid < Cout) {
        atomicAdd(&g_stats[tid], s1);
        atomicAdd(&g_stats[341 + tid], s2);
    }
}

__global__ void bn_finalize_kernel(int Cout, double inv_count) {
    int o = blockIdx.x * blockDim.x + threadIdx.x;
    if (o >= Cout) return;
    double mu  = g_stats[o] * inv_count;
    double var = g_stats[341 + o] * inv_count - mu * mu;
    g_mu[o]   = (float)mu;
    g_rstd[o] = (float)(1.0 / sqrt(var + 1e-5));
}

// pass2: BN + VN-LeakyReLU + mean over k -> writes BOTH feature layouts
__global__ void pass2_kernel(int cbase_out, int Cout,
                             const float* __restrict__ gamma, const float* __restrict__ beta) {
    int b = blockIdx.y, n = blockIdx.x;
    int o = threadIdx.x;
    if (o >= Cout) return;
    float mu = g_mu[o], rstd = g_rstd[o], gm = gamma[o], bt = beta[o];
    float a0 = 0, a1 = 0, a2 = 0;
    for (int k = 0; k < KNB; k++) {
        size_t base = ((((size_t)(b * NP + n)) * KNB + k) * Cout + o) * 3;
        float p0 = g_p[base], p1 = g_p[base + 1], p2 = g_p[base + 2];
        float d0 = g_d[base], d1 = g_d[base + 1], d2 = g_d[base + 2];
        float nor = sqrtf(p0 * p0 + p1 * p1 + p2 * p2) + EPSF;
        float s = ((nor - mu) * rstd * gm + bt) / nor;
        p0 *= s; p1 *= s; p2 *= s;
        float dot = p0 * d0 + p1 * d1 + p2 * d2;
        if (dot >= 0.f) {
            a0 += p0; a1 += p1; a2 += p2;
        } else {
            float dsq = d0 * d0 + d1 * d1 + d2 * d2;
            float f = 0.8f * dot / (dsq + EPSF);
            a0 += p0 - f * d0; a1 += p1 - f * d1; a2 += p2 - f * d2;
        }
    }
    const float inv = 1.f / (float)KNB;
    a0 *= inv; a1 *= inv; a2 *= inv;
    float* FO = g_feat + ((size_t)b * CT + cbase_out + o) * 3 * NP;
    FO[0 * NP + n] = a0;
    FO[1 * NP + n] = a1;
    FO[2 * NP + n] = a2;
    float* FT = g_featT + ((size_t)(b * NP + n) * CT + cbase_out + o) * 3;
    FT[0] = a0;
    FT[1] = a1;
    FT[2] = a2;
}

// layer 5: p5[b] (341x3072) = w5 (341x169) @ feat[b] (169x3072), into g_p
__global__ void __launch_bounds__(256) gemm_l5_kernel(const float* __restrict__ w5) {
    __shared__ float As[64][17];     // [m][k]
    __shared__ float Bs[16][64];     // [k][n]
    int b = blockIdx.z;
    const float* Bm = g_feat + (size_t)b * CT * 3 * NP;
    float* Cm = g_p + (size_t)b * 341 * 3072;
    int tid = threadIdx.x;
    int tx = tid & 15, ty = tid >> 4;
    int m0 = blockIdx.y * 64;
    int n0 = blockIdx.x * 64;
    float acc[4][4] = {};
    for (int k0 = 0; k0 < CT; k0 += 16) {
        for (int i = tid; i < 64 * 16; i += 256) {
            int k = i & 15, m = i >> 4;
            int gm_ = m0 + m, gk = k0 + k;
            As[m][k] = (gm_ < 341 && gk < CT) ? w5[gm_ * CT + gk] : 0.f;
        }
        for (int i = tid; i < 16 * 64; i += 256) {
            int nn = i & 63, k = i >> 6;
            int gk = k0 + k;
            Bs[k][nn] = (gk < CT) ? Bm[(size_t)gk * 3072 + n0 + nn] : 0.f;
        }
        __syncthreads();
#pragma unroll
        for (int kk = 0; kk < 16; kk++) {
            float a0 = As[ty * 4 + 0][kk];
            float a1 = As[ty * 4 + 1][kk];
            float a2 = As[ty * 4 + 2][kk];
            float a3 = As[ty * 4 + 3][kk];
            float b0 = Bs[kk][tx * 4 + 0];
            float b1 = Bs[kk][tx * 4 + 1];
            float b2 = Bs[kk][tx * 4 + 2];
            float b3 = Bs[kk][tx * 4 + 3];
            acc[0][0] += a0 * b0; acc[0][1] += a0 * b1; acc[0][2] += a0 * b2; acc[0][3] += a0 * b3;
            acc[1][0] += a1 * b0; acc[1][1] += a1 * b1; acc[1][2] += a1 * b2; acc[1][3] += a1 * b3;
            acc[2][0] += a2 * b0; acc[2][1] += a2 * b1; acc[2][2] += a2 * b2; acc[2][3] += a2 * b3;
            acc[3][0] += a3 * b0; acc[3][1] += a3 * b1; acc[3][2] += a3 * b2; acc[3][3] += a3 * b3;
        }
        __syncthreads();
    }
#pragma unroll
    for (int r = 0; r < 4; r++) {
        int gm_ = m0 + ty * 4 + r;
        if (gm_ < 341) {
#pragma unroll
            for (int s = 0; s < 4; s++)
                Cm[(size_t)gm_ * 3072 + n0 + tx * 4 + s] = acc[r][s];
        }
    }
}

__global__ void d5_kernel(const float* __restrict__ wd5) {
    int i = blockIdx.x * blockDim.x + threadIdx.x;   // B*3*N
    if (i >= BSZ * 3 * NP) return;
    int n = i % NP;
    int e = (i / NP) % 3;
    int b = i / (3 * NP);
    const float* F = g_feat + (size_t)b * CT * 3 * NP;
    float a = 0.f;
    for (int c = 0; c < CT; c++) a += wd5[c] * F[(size_t)(c * 3 + e) * NP + n];
    g_d[(size_t)b * 3072 + e * NP + n] = a;
}

__global__ void stats5_kernel() {
    int o = blockIdx.x, b = blockIdx.y;
    const float* P = g_p + ((size_t)b * 341 + o) * 3072;
    double s1 = 0.0, s2 = 0.0;
    for (int n = threadIdx.x; n < NP; n += blockDim.x) {
        float p0 = P[n], p1 = P[NP + n], p2 = P[2 * NP + n];
        float nor = sqrtf(p0 * p0 + p1 * p1 + p2 * p2) + EPSF;
        s1 += (double)nor;
        s2 += (double)nor * (double)nor;
    }
#pragma unroll
    for (int off = 16; off > 0; off >>= 1) {
        s1 += __shfl_down_sync(0xffffffff, s1, off);
        s2 += __shfl_down_sync(0xffffffff, s2, off);
    }
    if ((threadIdx.x & 31) == 0) {
        atomicAdd(&g_stats[o], s1);
        atomicAdd(&g_stats[341 + o], s2);
    }
}

__global__ void pass2_l5_kernel(float* __restrict__ out,
                                const float* __restrict__ gamma, const float* __restrict__ beta) {
    int i = blockIdx.x * blockDim.x + threadIdx.x;  // over B*341*N
    if (i >= BSZ * 341 * NP) return;
    int n = i % NP;
    int o = (i / NP) % 341;
    int b = i / (341 * NP);
    const float* P = g_p + ((size_t)b * 341 + o) * 3072;
    const float* D = g_d + (size_t)b * 3072;
    float p0 = P[n], p1 = P[NP + n], p2 = P[2 * NP + n];
    float d0 = D[n], d1 = D[NP + n], d2 = D[2 * NP + n];
    float nor = sqrtf(p0 * p0 + p1 * p1 + p2 * p2) + EPSF;
    float s = ((nor - g_mu[o]) * g_rstd[o] * gamma[o] + beta[o]) / nor;
    p0 *= s; p1 *= s; p2 *= s;
    float dot = p0 * d0 + p1 * d1 + p2 * d2;
    float v0, v1, v2;
    if (dot >= 0.f) {
        v0 = p0; v1 = p1; v2 = p2;
    } else {
        float dsq = d0 * d0 + d1 * d1 + d2 * d2;
        float f = 0.8f * dot / (dsq + EPSF);
        v0 = p0 - f * d0; v1 = p1 - f * d1; v2 = p2 - f * d2;
    }
    size_t ob = ((size_t)b * 341 + o) * 3072;
    out[ob + 0 * NP + n] = v0;
    out[ob + 1 * NP + n] = v1;
    out[ob + 2 * NP + n] = v2;
}

// ---------------- launch ----------------
extern "C" void kernel_launch(void* const* d_in, const int* in_sizes, int n_in,
                              void* d_out, int out_size) {
    const float* x = (const float*)d_in[0];
    const float *W[5], *Dw[5], *G[5], *Bt[5];
    for (int l = 0; l < 5; l++) {
        W[l]  = (const float*)d_in[1 + 4 * l];
        Dw[l] = (const float*)d_in[2 + 4 * l];
        G[l]  = (const float*)d_in[3 + 4 * l];
        Bt[l] = (const float*)d_in[4 + 4 * l];
    }
    float* out = (float*)d_out;

    void* pv;
    cudaGetSymbolAddress(&pv, g_h);
    float* hptr = (float*)pv;
    cudaGetSymbolAddress(&pv, g_feat);
    float* fptr = (float*)pv;
    cudaGetSymbolAddress(&pv, g_featT);
    float* ftptr = (float*)pv;

    cudaFuncSetAttribute(pass1_kernel, cudaFuncAttributeMaxDynamicSharedMemorySize, 100 * 1024);

    transpose_x_kernel<<<96, 256>>>(x);

    struct LayerCfg { const float* feat; const float* ft; int ps; int cb3; int D; int C; int Cout; int cbo; };
    LayerCfg L[4] = {
        { hptr,               x,     3,      0,      3,   1,  21, 0  },
        { fptr,               ftptr, CT * 3, 0,      63,  21, 21, 21 },
        { fptr + 21 * 3 * NP, ftptr, CT * 3, 21 * 3, 63,  21, 42, 42 },
        { fptr + 42 * 3 * NP, ftptr, CT * 3, 42 * 3, 126, 42, 85, 84 },
    };

    for (int l = 0; l < 4; l++) {
        int bstride = (l == 0) ? 3 * NP : CT * 3 * NP;
        int D = L[l].D;
        xx_kernel<<<dim3(NP / 256, BSZ), 256>>>(L[l].feat, bstride, D);
        size_t smem_k = (size_t)(D * RPB + NP + 8 * NP) * sizeof(float);
        knn_fused_kernel<<<dim3(NP / RPB, BSZ), 256, smem_k>>>(L[l].feat, bstride, D);
        zero_stats_kernel<<<1, 682>>>();
        int C = L[l].C, Co = L[l].Cout;
        size_t smem = (size_t)(4 * Co * C + C * 3 + KNB * C * 3 + KNB * Co * 3) * sizeof(float);
        pass1_kernel<<<dim3(NP / NT, BSZ), 256, smem>>>(L[l].ft, L[l].ps, L[l].cb3, C, Co, W[l], Dw[l]);
        bn_finalize_kernel<<<3, 128>>>(Co, 1.0 / ((double)BSZ * NP * KNB));
        int p2threads = ((Co + 31) / 32) * 32;
        pass2_kernel<<<dim3(NP, BSZ), p2threads>>>(L[l].cbo, Co, G[l], Bt[l]);
    }

    // layer 5
    zero_stats_kernel<<<1, 682>>>();
    gemm_l5_kernel<<<dim3(3072 / 64, (341 + 63) / 64, BSZ), 256>>>(W[4]);
    d5_kernel<<<96, 256>>>(Dw[4]);
    stats5_kernel<<<dim3(341, BSZ), 256>>>();
    bn_finalize_kernel<<<3, 128>>>(341, 1.0 / ((double)BSZ * NP));
    pass2_l5_kernel<<<(BSZ * 341 * NP + 255) / 256, 256>>>(out, G[4], Bt[4]);
}